// round 5
// baseline (speedup 1.0000x reference)
#include <cuda_runtime.h>
#include <cstdint>

// GIN_38216619000492: GINConv (eps=0) + 2-layer MLP
//   h = x + segment_sum(x[src], dst)          [N,64]
//   hid = relu(h @ W1 + b1)                   [N,256]
//   out = hid @ W2 + b2                       [N,64]
// N=50000, E=800000. x/W/b fp32; edge_index is INT32 (JAX x64-disabled
// downcasts the reference's jnp.int64 -> int32; reading it as int64 was the
// R3 illegal-memory-access).

#define D_IN  64
#define D_H   256
#define D_OUT 64
#define NMAX  50000

// Scratch for aggregated features (allocation-free rule: __device__ global).
static __device__ float g_h[(size_t)NMAX * D_IN];

// ---------------------------------------------------------------------------
// Kernel 1: h = x  (eps=0 so (1+eps)*x == x; scatter adds neighbors on top)
// ---------------------------------------------------------------------------
__global__ void gin_copy(const float* __restrict__ x, int n4) {
    int i = blockIdx.x * blockDim.x + threadIdx.x;
    if (i < n4) ((float4*)g_h)[i] = ((const float4*)x)[i];
}

// ---------------------------------------------------------------------------
// Kernel 2: scatter-add. 16 threads per edge, one float4 chunk each.
// Consecutive threads touch consecutive 16B of the same edge row -> coalesced
// 256B gather + 256B scatter per edge. x and g_h are L2-resident (12.8MB each).
// red.global.add.v4.f32 = one issued op per 16B (4x fewer than scalar
// atomicAdd; no return value needed).
// ---------------------------------------------------------------------------
__global__ void gin_scatter(const float* __restrict__ x,
                            const int* __restrict__ ei, int E) {
    int w = blockIdx.x * blockDim.x + threadIdx.x;
    int e = w >> 4;
    if (e >= E) return;
    int c = (w & 15) << 2;
    int src = ei[e];
    int dst = ei[E + e];
    float4 v = *(const float4*)(x + (size_t)src * D_IN + c);
    float* o = g_h + (size_t)dst * D_IN + c;
    asm volatile("red.global.add.v4.f32 [%0], {%1, %2, %3, %4};"
                 :: "l"(o), "f"(v.x), "f"(v.y), "f"(v.z), "f"(v.w)
                 : "memory");
}

// ---------------------------------------------------------------------------
// Kernel 3: fused MLP. One block handles 64 rows. W1, W2, biases, h-tile and
// the hidden activation tile all live in shared memory (216,320 B dynamic).
//
// Shared layout (float offsets):
//   W1s  @     0 : [64][256]          (65536 B)
//   W2s  @ 16384 : [256][64]          (65536 B)
//   b1s  @ 32768 : [256]
//   b2s  @ 33024 : [64]
//   hs   @ 33088 : [64][68]  (pad 68 kills r-stride bank conflicts) (17408 B)
//   hid  @ 37440 : [64][260] (pad 260, 16B-aligned rows)            (66560 B)
// total floats = 54080 -> 216320 bytes.
// ---------------------------------------------------------------------------
#define SMEM_FLOATS 54080
#define SMEM_BYTES  (SMEM_FLOATS * 4)

__global__ __launch_bounds__(256, 1)
void gin_mlp(const float* __restrict__ W1, const float* __restrict__ b1,
             const float* __restrict__ W2, const float* __restrict__ b2,
             float* __restrict__ out, int N) {
    extern __shared__ float s[];
    float* W1s = s;               // [64][256]
    float* W2s = s + 16384;       // [256][64]
    float* b1s = s + 32768;       // [256]
    float* b2s = s + 33024;       // [64]
    float* hs  = s + 33088;       // [64][68]
    float* hid = s + 37440;       // [64][260]

    const int t = threadIdx.x;

    // Stage weights/biases (float4, fully coalesced).
    {
        const float4* W1v = (const float4*)W1;
        float4* W1sv = (float4*)W1s;
        #pragma unroll 4
        for (int i = t; i < 4096; i += 256) W1sv[i] = W1v[i];
        const float4* W2v = (const float4*)W2;
        float4* W2sv = (float4*)W2s;
        #pragma unroll 4
        for (int i = t; i < 4096; i += 256) W2sv[i] = W2v[i];
        if (t < 64) ((float4*)b1s)[t] = ((const float4*)b1)[t];
        if (t < 16) ((float4*)b2s)[t] = ((const float4*)b2)[t];
    }

    // Stage the 64-row h tile (zero-pad past N; those rows are never stored).
    const int row0 = blockIdx.x * 64;
    for (int i = t; i < 1024; i += 256) {        // 64 rows x 16 float4
        int r = i >> 4, c = (i & 15) << 2;
        float4 v = make_float4(0.f, 0.f, 0.f, 0.f);
        int gr = row0 + r;
        if (gr < N) v = *(const float4*)(g_h + (size_t)gr * D_IN + c);
        *(float4*)(hs + r * 68 + c) = v;
    }
    __syncthreads();

    // ---------------- Phase A: hid = relu(h @ W1 + b1) ----------------
    // Thread tile: 4 rows x 16 cols. Rows: (t>>4)*4. Cols: ci + 64*m,
    // m=0..3 -> consecutive threads read consecutive float4s of W1 (no bank
    // conflicts); h reads are warp-broadcast.
    {
        const int ra = (t >> 4) * 4;
        const int ci = (t & 15) * 4;
        float acc[4][16];
        #pragma unroll
        for (int a = 0; a < 4; a++)
            #pragma unroll
            for (int b = 0; b < 16; b++) acc[a][b] = 0.f;

        #pragma unroll 2
        for (int k = 0; k < 64; k += 4) {
            float4 hv[4];
            #pragma unroll
            for (int rr = 0; rr < 4; rr++)
                hv[rr] = *(const float4*)(hs + (ra + rr) * 68 + k);
            #pragma unroll
            for (int kk = 0; kk < 4; kk++) {
                #pragma unroll
                for (int m = 0; m < 4; m++) {
                    float4 w = *(const float4*)(W1s + (k + kk) * 256 + ci + m * 64);
                    #pragma unroll
                    for (int rr = 0; rr < 4; rr++) {
                        float hval = ((const float*)&hv[rr])[kk];
                        acc[rr][m * 4 + 0] = fmaf(hval, w.x, acc[rr][m * 4 + 0]);
                        acc[rr][m * 4 + 1] = fmaf(hval, w.y, acc[rr][m * 4 + 1]);
                        acc[rr][m * 4 + 2] = fmaf(hval, w.z, acc[rr][m * 4 + 2]);
                        acc[rr][m * 4 + 3] = fmaf(hval, w.w, acc[rr][m * 4 + 3]);
                    }
                }
            }
        }

        #pragma unroll
        for (int m = 0; m < 4; m++) {
            int c0 = ci + m * 64;
            float4 bb = *(const float4*)(b1s + c0);
            #pragma unroll
            for (int rr = 0; rr < 4; rr++) {
                float4 v;
                v.x = fmaxf(acc[rr][m * 4 + 0] + bb.x, 0.f);
                v.y = fmaxf(acc[rr][m * 4 + 1] + bb.y, 0.f);
                v.z = fmaxf(acc[rr][m * 4 + 2] + bb.z, 0.f);
                v.w = fmaxf(acc[rr][m * 4 + 3] + bb.w, 0.f);
                *(float4*)(hid + (ra + rr) * 260 + c0) = v;
            }
        }
    }
    __syncthreads();

    // ---------------- Phase B: out = hid @ W2 + b2 ----------------
    // Thread tile: 4 rows x 4 cols; consecutive threads read consecutive
    // float4s of W2 row k (conflict-free); hid reads warp-broadcast.
    {
        const int rb = (t >> 4) * 4;
        const int cb = (t & 15) * 4;
        float acc[4][4];
        #pragma unroll
        for (int a = 0; a < 4; a++)
            #pragma unroll
            for (int b = 0; b < 4; b++) acc[a][b] = 0.f;

        for (int k = 0; k < 256; k += 4) {
            float4 hv[4], wv[4];
            #pragma unroll
            for (int rr = 0; rr < 4; rr++)
                hv[rr] = *(const float4*)(hid + (rb + rr) * 260 + k);
            #pragma unroll
            for (int kk = 0; kk < 4; kk++)
                wv[kk] = *(const float4*)(W2s + (k + kk) * 64 + cb);
            #pragma unroll
            for (int kk = 0; kk < 4; kk++) {
                #pragma unroll
                for (int rr = 0; rr < 4; rr++) {
                    float hval = ((const float*)&hv[rr])[kk];
                    acc[rr][0] = fmaf(hval, wv[kk].x, acc[rr][0]);
                    acc[rr][1] = fmaf(hval, wv[kk].y, acc[rr][1]);
                    acc[rr][2] = fmaf(hval, wv[kk].z, acc[rr][2]);
                    acc[rr][3] = fmaf(hval, wv[kk].w, acc[rr][3]);
                }
            }
        }

        float4 bb = *(const float4*)(b2s + cb);
        #pragma unroll
        for (int rr = 0; rr < 4; rr++) {
            int gr = row0 + rb + rr;
            if (gr < N) {
                float4 v;
                v.x = acc[rr][0] + bb.x;
                v.y = acc[rr][1] + bb.y;
                v.z = acc[rr][2] + bb.z;
                v.w = acc[rr][3] + bb.w;
                *(float4*)(out + (size_t)gr * D_OUT + cb) = v;
            }
        }
    }
}

// ---------------------------------------------------------------------------
// Launch. Inputs per metadata order: x[f32], edge_index[i32 2xE], W1, b1, W2, b2.
// ---------------------------------------------------------------------------
extern "C" void kernel_launch(void* const* d_in, const int* in_sizes, int n_in,
                              void* d_out, int out_size) {
    const float* x  = (const float*)d_in[0];
    const int*   ei = (const int*)d_in[1];      // int32! (JAX x64 off)
    const float* W1 = (const float*)d_in[2];
    const float* b1 = (const float*)d_in[3];
    const float* W2 = (const float*)d_in[4];
    const float* b2 = (const float*)d_in[5];
    float* out = (float*)d_out;

    const int N = in_sizes[0] / D_IN;   // 50000
    const int E = in_sizes[1] / 2;      // 800000

    cudaFuncSetAttribute(gin_mlp, cudaFuncAttributeMaxDynamicSharedMemorySize,
                         SMEM_BYTES);

    int n4 = N * (D_IN / 4);
    gin_copy<<<(n4 + 255) / 256, 256>>>(x, n4);

    int work = E * 16;                  // 16 float4 chunks per edge
    gin_scatter<<<(work + 255) / 256, 256>>>(x, ei, E);

    gin_mlp<<<(N + 63) / 64, 256, SMEM_BYTES>>>(W1, b1, W2, b2, out, N);
}

// round 7
// speedup vs baseline: 1.7857x; 1.7857x over previous
#include <cuda_runtime.h>
#include <cstdint>

// GIN_38216619000492: GINConv (eps=0) + 2-layer MLP.
//   h = x + segment_sum(x[src], dst)          [N,64]
//   hid = relu(h @ W1 + b1)                   [N,256]
//   out = hid @ W2 + b2                       [N,64]
// N=50000, E=800000, edge_index int32.
// MLP via mma.sync tf32 (base sm_100 target: tcgen05 is 'a'-suffix-gated and
// unavailable; mma.sync.m16n8k8.tf32 is sm_80+ baseline and hits the tensor pipe).

#define D_IN  64
#define D_H   256
#define D_OUT 64
#define NMAX  50000

static __device__ float g_h[(size_t)NMAX * D_IN];
static __device__ float g_B1[17408];   // W1^T tf32 image: [n=256][k=64], stride 68
static __device__ float g_B2[16640];   // W2^T tf32 image: [n=64][k=256], stride 260

__device__ __forceinline__ uint32_t f2tf32(float f) {
    uint32_t u;
    asm("cvt.rna.tf32.f32 %0, %1;" : "=r"(u) : "f"(f));
    return u;
}

__device__ __forceinline__ void mma8(float* c, uint32_t a0, uint32_t a1,
                                     uint32_t a2, uint32_t a3,
                                     uint32_t b0, uint32_t b1) {
    asm volatile(
        "mma.sync.aligned.m16n8k8.row.col.f32.tf32.tf32.f32 "
        "{%0,%1,%2,%3}, {%4,%5,%6,%7}, {%8,%9}, {%0,%1,%2,%3};"
        : "+f"(c[0]), "+f"(c[1]), "+f"(c[2]), "+f"(c[3])
        : "r"(a0), "r"(a1), "r"(a2), "r"(a3), "r"(b0), "r"(b1));
}

// ---------------------------------------------------------------------------
// Kernel 1: h = x   (eps=0)
// ---------------------------------------------------------------------------
__global__ void gin_copy(const float* __restrict__ x, int n4) {
    int i = blockIdx.x * blockDim.x + threadIdx.x;
    if (i < n4) ((float4*)g_h)[i] = ((const float4*)x)[i];
}

// ---------------------------------------------------------------------------
// Kernel 1b: transpose + tf32-convert weights into strided global images.
//   g_B1[n*68+k]  = tf32(W1[k][n])   k<64,  n<256
//   g_B2[n*260+k] = tf32(W2[k][n])   k<256, n<64
// Strides 68/260 are ≡4 (mod 32) floats -> conflict-free fragment LDS.
// ---------------------------------------------------------------------------
__global__ void gin_prep(const float* __restrict__ W1, const float* __restrict__ W2) {
    int i = blockIdx.x * blockDim.x + threadIdx.x;
    if (i >= 32768) return;
    if (i < 16384) {
        int k = i >> 8, n = i & 255;
        ((uint32_t*)g_B1)[n * 68 + k] = f2tf32(W1[i]);
    } else {
        int j = i - 16384;
        int k = j >> 6, n = j & 63;
        ((uint32_t*)g_B2)[n * 260 + k] = f2tf32(W2[j]);
    }
}

// ---------------------------------------------------------------------------
// Kernel 2: scatter-add, red.global.add.v4.f32, 16 threads/edge (R5-proven).
// ---------------------------------------------------------------------------
__global__ void gin_scatter(const float* __restrict__ x,
                            const int* __restrict__ ei, int E) {
    int w = blockIdx.x * blockDim.x + threadIdx.x;
    int e = w >> 4;
    if (e >= E) return;
    int c = (w & 15) << 2;
    int src = ei[e];
    int dst = ei[E + e];
    float4 v = *(const float4*)(x + (size_t)src * D_IN + c);
    float* o = g_h + (size_t)dst * D_IN + c;
    asm volatile("red.global.add.v4.f32 [%0], {%1, %2, %3, %4};"
                 :: "l"(o), "f"(v.x), "f"(v.y), "f"(v.z), "f"(v.w)
                 : "memory");
}

// ---------------------------------------------------------------------------
// Kernel 3: fused MLP, tf32 mma.sync. 128 rows/CTA, 8 warps.
// SMEM (float offsets):
//   phase1: hs  @ 0     [128][68]      (34,816 B)
//           B1  @ 8704  [256][68]      (69,632 B)
//   phase2: hid rows 0..95  @ 0        (stride 260; fits in 104,448 B)
//           hid rows 96..127 @ 42752
//   B2  @ 26112 [64][260]              (66,560 B, disjoint from phase1 -> staged early)
//   b1s @ 51072 [256], b2s @ 51328 [64]
// total 51,392 floats = 205,568 B.
// ---------------------------------------------------------------------------
#define HS_F    0
#define B1_F    8704
#define HID0_F  0
#define B2_F    26112
#define HID1_F  42752
#define B1S_F   51072
#define B2S_F   51328
#define SMEM_BYTES (51392 * 4)

__device__ __forceinline__ int hid_off(int r) {
    return (r < 96) ? (HID0_F + r * 260) : (HID1_F + (r - 96) * 260);
}

__global__ __launch_bounds__(256, 1)
void gin_mlp(const float* __restrict__ b1, const float* __restrict__ b2,
             float* __restrict__ out, int N) {
    extern __shared__ float s[];
    uint32_t* su = (uint32_t*)s;

    const int t = threadIdx.x;
    const int w = t >> 5;
    const int lane = t & 31;
    const int g = lane >> 2;      // group id (0..7)
    const int tg = lane & 3;      // thread-in-group (0..3)
    const int row0 = blockIdx.x * 128;

    // ---- Stage B1, B2, biases (float4 memcpy of pre-built images) ----
    {
        const float4* g1 = (const float4*)g_B1;
        const float4* g2 = (const float4*)g_B2;
        float4* s1 = (float4*)(s + B1_F);
        float4* s2 = (float4*)(s + B2_F);
        #pragma unroll 4
        for (int i = t; i < 4352; i += 256) s1[i] = g1[i];
        #pragma unroll 4
        for (int i = t; i < 4160; i += 256) s2[i] = g2[i];
        if (t < 64) ((float4*)(s + B1S_F))[t] = ((const float4*)b1)[t];
        if (t < 16) ((float4*)(s + B2S_F))[t] = ((const float4*)b2)[t];
    }

    // ---- Stage A1 = tf32(h tile) [128][68] ----
    for (int i = t; i < 2048; i += 256) {          // 128 rows x 16 float4
        int r = i >> 4, k4 = (i & 15) << 2;
        float4 v = make_float4(0.f, 0.f, 0.f, 0.f);
        int gr = row0 + r;
        if (gr < N) v = *(const float4*)(g_h + (size_t)gr * D_IN + k4);
        uint4 u = make_uint4(f2tf32(v.x), f2tf32(v.y), f2tf32(v.z), f2tf32(v.w));
        *(uint4*)(s + HS_F + r * 68 + k4) = u;
    }
    __syncthreads();

    // ---- GEMM1: D1[128,256] = A1[128,64] @ B1^T ; all 128 acc in regs ----
    float acc[32][4];
    #pragma unroll
    for (int nt = 0; nt < 32; nt++)
        #pragma unroll
        for (int j = 0; j < 4; j++) acc[nt][j] = 0.f;

    {
        const uint32_t* arow_lo = su + HS_F + (16 * w + g) * 68;
        const uint32_t* arow_hi = arow_lo + 8 * 68;
        const uint32_t* Bb = su + B1_F + g * 68;   // n = nt*8 + g
        for (int ks = 0; ks < 8; ks++) {
            int kb = ks * 8;
            uint32_t a0 = arow_lo[kb + tg];
            uint32_t a1 = arow_hi[kb + tg];
            uint32_t a2 = arow_lo[kb + tg + 4];
            uint32_t a3 = arow_hi[kb + tg + 4];
            #pragma unroll
            for (int nt = 0; nt < 32; nt++) {
                uint32_t b0 = Bb[nt * 8 * 68 + kb + tg];
                uint32_t b1v = Bb[nt * 8 * 68 + kb + tg + 4];
                mma8(acc[nt], a0, a1, a2, a3, b0, b1v);
            }
        }
    }
    __syncthreads();   // everyone done reading hs/B1; hid may now alias them

    // ---- Epilogue 1: hid = tf32(relu(D1 + b1)) ----
    {
        const int r_lo = 16 * w + g;
        float* h_lo = s + hid_off(r_lo);
        float* h_hi = s + hid_off(r_lo + 8);
        #pragma unroll
        for (int nt = 0; nt < 32; nt++) {
            int col = nt * 8 + 2 * tg;
            float bb0 = s[B1S_F + col], bb1 = s[B1S_F + col + 1];
            uint2 u0, u1;
            u0.x = f2tf32(fmaxf(acc[nt][0] + bb0, 0.f));
            u0.y = f2tf32(fmaxf(acc[nt][1] + bb1, 0.f));
            u1.x = f2tf32(fmaxf(acc[nt][2] + bb0, 0.f));
            u1.y = f2tf32(fmaxf(acc[nt][3] + bb1, 0.f));
            *(uint2*)(h_lo + col) = u0;
            *(uint2*)(h_hi + col) = u1;
        }
    }
    __syncthreads();   // cheap; guarantees cross-lane hid visibility

    // ---- GEMM2: D2[128,64] = A2[128,256] @ B2^T ----
    float acc2[8][4];
    #pragma unroll
    for (int nt = 0; nt < 8; nt++)
        #pragma unroll
        for (int j = 0; j < 4; j++) acc2[nt][j] = 0.f;

    {
        const uint32_t* arow_lo = su + hid_off(16 * w + g);
        const uint32_t* arow_hi = su + hid_off(16 * w + g + 8);
        const uint32_t* Bb = su + B2_F + g * 260;  // n = nt*8 + g
        for (int ks = 0; ks < 32; ks++) {
            int kb = ks * 8;
            uint32_t a0 = arow_lo[kb + tg];
            uint32_t a1 = arow_hi[kb + tg];
            uint32_t a2 = arow_lo[kb + tg + 4];
            uint32_t a3 = arow_hi[kb + tg + 4];
            #pragma unroll
            for (int nt = 0; nt < 8; nt++) {
                uint32_t b0 = Bb[nt * 8 * 260 + kb + tg];
                uint32_t b1v = Bb[nt * 8 * 260 + kb + tg + 4];
                mma8(acc2[nt], a0, a1, a2, a3, b0, b1v);
            }
        }
    }

    // ---- Epilogue 2: out = D2 + b2 (fp32) ----
    {
        int gr_lo = row0 + 16 * w + g;
        int gr_hi = gr_lo + 8;
        #pragma unroll
        for (int nt = 0; nt < 8; nt++) {
            int col = nt * 8 + 2 * tg;
            float bb0 = s[B2S_F + col], bb1 = s[B2S_F + col + 1];
            if (gr_lo < N) {
                float2 v = make_float2(acc2[nt][0] + bb0, acc2[nt][1] + bb1);
                *(float2*)(out + (size_t)gr_lo * D_OUT + col) = v;
            }
            if (gr_hi < N) {
                float2 v = make_float2(acc2[nt][2] + bb0, acc2[nt][3] + bb1);
                *(float2*)(out + (size_t)gr_hi * D_OUT + col) = v;
            }
        }
    }
}

// ---------------------------------------------------------------------------
// Launch. Inputs: x[f32], edge_index[i32 2xE], W1, b1, W2, b2.
// ---------------------------------------------------------------------------
extern "C" void kernel_launch(void* const* d_in, const int* in_sizes, int n_in,
                              void* d_out, int out_size) {
    const float* x  = (const float*)d_in[0];
    const int*   ei = (const int*)d_in[1];
    const float* W1 = (const float*)d_in[2];
    const float* b1 = (const float*)d_in[3];
    const float* W2 = (const float*)d_in[4];
    const float* b2 = (const float*)d_in[5];
    float* out = (float*)d_out;

    const int N = in_sizes[0] / D_IN;   // 50000
    const int E = in_sizes[1] / 2;      // 800000

    cudaFuncSetAttribute(gin_mlp, cudaFuncAttributeMaxDynamicSharedMemorySize,
                         SMEM_BYTES);

    int n4 = N * (D_IN / 4);
    gin_copy<<<(n4 + 255) / 256, 256>>>(x, n4);
    gin_prep<<<128, 256>>>(W1, W2);

    int work = E * 16;
    gin_scatter<<<(work + 255) / 256, 256>>>(x, ei, E);

    gin_mlp<<<(N + 127) / 128, 256, SMEM_BYTES>>>(b1, b2, out, N);
}

// round 8
// speedup vs baseline: 1.9661x; 1.1010x over previous
#include <cuda_runtime.h>
#include <cstdint>

// GIN_38216619000492: GINConv (eps=0) + 2-layer MLP.
//   h = x + segment_sum(x[src], dst)          [N,64]
//   hid = relu(h @ W1 + b1)                   [N,256]
//   out = hid @ W2 + b2                       [N,64]
// N=50000, E=800000, edge_index int32.
// MLP via mma.sync tf32 (base sm_100 target; tcgen05 is 'a'-gated).
// R8: 16 warps/CTA (was 8), n-range split across warp halves -> 2x issue width.

#define D_IN  64
#define D_H   256
#define D_OUT 64
#define NMAX  50000

static __device__ float g_h[(size_t)NMAX * D_IN];
static __device__ float g_B1[17408];   // W1^T tf32 image: [n=256][k=64], stride 68
static __device__ float g_B2[16640];   // W2^T tf32 image: [n=64][k=256], stride 260

__device__ __forceinline__ uint32_t f2tf32(float f) {
    uint32_t u;
    asm("cvt.rna.tf32.f32 %0, %1;" : "=r"(u) : "f"(f));
    return u;
}

__device__ __forceinline__ void mma8(float* c, uint32_t a0, uint32_t a1,
                                     uint32_t a2, uint32_t a3,
                                     uint32_t b0, uint32_t b1) {
    asm volatile(
        "mma.sync.aligned.m16n8k8.row.col.f32.tf32.tf32.f32 "
        "{%0,%1,%2,%3}, {%4,%5,%6,%7}, {%8,%9}, {%0,%1,%2,%3};"
        : "+f"(c[0]), "+f"(c[1]), "+f"(c[2]), "+f"(c[3])
        : "r"(a0), "r"(a1), "r"(a2), "r"(a3), "r"(b0), "r"(b1));
}

// ---------------------------------------------------------------------------
// Kernel 1: h = x   (eps=0)
// ---------------------------------------------------------------------------
__global__ void gin_copy(const float* __restrict__ x, int n4) {
    int i = blockIdx.x * blockDim.x + threadIdx.x;
    if (i < n4) ((float4*)g_h)[i] = ((const float4*)x)[i];
}

// ---------------------------------------------------------------------------
// Kernel 1b: transpose + tf32-convert weights into strided global images.
// ---------------------------------------------------------------------------
__global__ void gin_prep(const float* __restrict__ W1, const float* __restrict__ W2) {
    int i = blockIdx.x * blockDim.x + threadIdx.x;
    if (i >= 32768) return;
    if (i < 16384) {
        int k = i >> 8, n = i & 255;
        ((uint32_t*)g_B1)[n * 68 + k] = f2tf32(W1[i]);
    } else {
        int j = i - 16384;
        int k = j >> 6, n = j & 63;
        ((uint32_t*)g_B2)[n * 260 + k] = f2tf32(W2[j]);
    }
}

// ---------------------------------------------------------------------------
// Kernel 2: scatter-add, red.global.add.v4.f32, 16 threads/edge (proven).
// ---------------------------------------------------------------------------
__global__ void gin_scatter(const float* __restrict__ x,
                            const int* __restrict__ ei, int E) {
    int w = blockIdx.x * blockDim.x + threadIdx.x;
    int e = w >> 4;
    if (e >= E) return;
    int c = (w & 15) << 2;
    int src = ei[e];
    int dst = ei[E + e];
    float4 v = *(const float4*)(x + (size_t)src * D_IN + c);
    float* o = g_h + (size_t)dst * D_IN + c;
    asm volatile("red.global.add.v4.f32 [%0], {%1, %2, %3, %4};"
                 :: "l"(o), "f"(v.x), "f"(v.y), "f"(v.z), "f"(v.w)
                 : "memory");
}

// ---------------------------------------------------------------------------
// Kernel 3: fused MLP, tf32 mma.sync. 128 rows/CTA, 16 warps (512 thr).
// Warp w: m-group mw = w&7 (rows 16mw..16mw+16), n-half nh = w>>3.
//   GEMM1: nt in [nh*16, nh*16+16);  GEMM2: nt in [nh*4, nh*4+4).
// SMEM layout identical to R7 (205,568 B, validated):
//   phase1: hs @0 [128][68], B1 @8704 [256][68]
//   phase2: hid rows 0..95 @0 (stride 260), rows 96..127 @42752
//   B2 @26112 [64][260]; b1s @51072; b2s @51328.
// ---------------------------------------------------------------------------
#define HS_F    0
#define B1_F    8704
#define HID0_F  0
#define B2_F    26112
#define HID1_F  42752
#define B1S_F   51072
#define B2S_F   51328
#define SMEM_BYTES (51392 * 4)

__device__ __forceinline__ int hid_off(int r) {
    return (r < 96) ? (HID0_F + r * 260) : (HID1_F + (r - 96) * 260);
}

__global__ __launch_bounds__(512, 1)
void gin_mlp(const float* __restrict__ b1, const float* __restrict__ b2,
             float* __restrict__ out, int N) {
    extern __shared__ float s[];
    uint32_t* su = (uint32_t*)s;

    const int t = threadIdx.x;
    const int w = t >> 5;
    const int mw = w & 7;         // m-group: rows 16mw..16mw+16
    const int nh = w >> 3;        // n-half
    const int lane = t & 31;
    const int g = lane >> 2;      // group id (0..7)
    const int tg = lane & 3;      // thread-in-group (0..3)
    const int row0 = blockIdx.x * 128;

    // ---- Stage B1, B2, biases ----
    {
        const float4* g1 = (const float4*)g_B1;
        const float4* g2 = (const float4*)g_B2;
        float4* s1 = (float4*)(s + B1_F);
        float4* s2 = (float4*)(s + B2_F);
        #pragma unroll 4
        for (int i = t; i < 4352; i += 512) s1[i] = g1[i];
        #pragma unroll 4
        for (int i = t; i < 4160; i += 512) s2[i] = g2[i];
        if (t < 64) ((float4*)(s + B1S_F))[t] = ((const float4*)b1)[t];
        if (t < 16) ((float4*)(s + B2S_F))[t] = ((const float4*)b2)[t];
    }

    // ---- Stage A1 = tf32(h tile) [128][68] ----
    #pragma unroll 4
    for (int i = t; i < 2048; i += 512) {          // 128 rows x 16 float4
        int r = i >> 4, k4 = (i & 15) << 2;
        float4 v = make_float4(0.f, 0.f, 0.f, 0.f);
        int gr = row0 + r;
        if (gr < N) v = *(const float4*)(g_h + (size_t)gr * D_IN + k4);
        uint4 u = make_uint4(f2tf32(v.x), f2tf32(v.y), f2tf32(v.z), f2tf32(v.w));
        *(uint4*)(s + HS_F + r * 68 + k4) = u;
    }
    __syncthreads();

    // ---- GEMM1: warp computes rows [16mw,16mw+16) x cols [nh*128, nh*128+128) ----
    float acc[16][4];
    #pragma unroll
    for (int nt = 0; nt < 16; nt++)
        #pragma unroll
        for (int j = 0; j < 4; j++) acc[nt][j] = 0.f;

    {
        const uint32_t* arow_lo = su + HS_F + (16 * mw + g) * 68;
        const uint32_t* arow_hi = arow_lo + 8 * 68;
        const uint32_t* Bb = su + B1_F + (nh * 128 + g) * 68;   // n = nh*128 + ntl*8 + g
        #pragma unroll
        for (int ks = 0; ks < 8; ks++) {
            int kb = ks * 8;
            uint32_t a0 = arow_lo[kb + tg];
            uint32_t a1 = arow_hi[kb + tg];
            uint32_t a2 = arow_lo[kb + tg + 4];
            uint32_t a3 = arow_hi[kb + tg + 4];
            // chunk nt loop (2x8) to bound live B fragments
            #pragma unroll
            for (int c8 = 0; c8 < 2; c8++) {
                uint32_t bv[8][2];
                #pragma unroll
                for (int q = 0; q < 8; q++) {
                    int ntl = c8 * 8 + q;
                    bv[q][0] = Bb[ntl * 8 * 68 + kb + tg];
                    bv[q][1] = Bb[ntl * 8 * 68 + kb + tg + 4];
                }
                #pragma unroll
                for (int q = 0; q < 8; q++)
                    mma8(acc[c8 * 8 + q], a0, a1, a2, a3, bv[q][0], bv[q][1]);
            }
        }
    }
    __syncthreads();   // all reads of hs/B1 done; hid may alias them

    // ---- Epilogue 1: hid = tf32(relu(D1 + b1)) ----
    {
        const int r_lo = 16 * mw + g;
        float* h_lo = s + hid_off(r_lo);
        float* h_hi = s + hid_off(r_lo + 8);
        #pragma unroll
        for (int ntl = 0; ntl < 16; ntl++) {
            int col = (nh * 16 + ntl) * 8 + 2 * tg;
            float bb0 = s[B1S_F + col], bb1 = s[B1S_F + col + 1];
            uint2 u0, u1;
            u0.x = f2tf32(fmaxf(acc[ntl][0] + bb0, 0.f));
            u0.y = f2tf32(fmaxf(acc[ntl][1] + bb1, 0.f));
            u1.x = f2tf32(fmaxf(acc[ntl][2] + bb0, 0.f));
            u1.y = f2tf32(fmaxf(acc[ntl][3] + bb1, 0.f));
            *(uint2*)(h_lo + col) = u0;
            *(uint2*)(h_hi + col) = u1;
        }
    }
    __syncthreads();

    // ---- GEMM2: warp computes rows [16mw,16mw+16) x cols [nh*32, nh*32+32) ----
    float acc2[4][4];
    #pragma unroll
    for (int nt = 0; nt < 4; nt++)
        #pragma unroll
        for (int j = 0; j < 4; j++) acc2[nt][j] = 0.f;

    {
        const uint32_t* arow_lo = su + hid_off(16 * mw + g);
        const uint32_t* arow_hi = su + hid_off(16 * mw + g + 8);
        const uint32_t* Bb = su + B2_F + (nh * 32 + g) * 260;   // n = nh*32 + ntl*8 + g
        #pragma unroll 4
        for (int ks = 0; ks < 32; ks++) {
            int kb = ks * 8;
            uint32_t a0 = arow_lo[kb + tg];
            uint32_t a1 = arow_hi[kb + tg];
            uint32_t a2 = arow_lo[kb + tg + 4];
            uint32_t a3 = arow_hi[kb + tg + 4];
            uint32_t bv[4][2];
            #pragma unroll
            for (int q = 0; q < 4; q++) {
                bv[q][0] = Bb[q * 8 * 260 + kb + tg];
                bv[q][1] = Bb[q * 8 * 260 + kb + tg + 4];
            }
            #pragma unroll
            for (int q = 0; q < 4; q++)
                mma8(acc2[q], a0, a1, a2, a3, bv[q][0], bv[q][1]);
        }
    }

    // ---- Epilogue 2: out = D2 + b2 (fp32) ----
    {
        int gr_lo = row0 + 16 * mw + g;
        int gr_hi = gr_lo + 8;
        #pragma unroll
        for (int ntl = 0; ntl < 4; ntl++) {
            int col = (nh * 4 + ntl) * 8 + 2 * tg;
            float bb0 = s[B2S_F + col], bb1 = s[B2S_F + col + 1];
            if (gr_lo < N) {
                float2 v = make_float2(acc2[ntl][0] + bb0, acc2[ntl][1] + bb1);
                *(float2*)(out + (size_t)gr_lo * D_OUT + col) = v;
            }
            if (gr_hi < N) {
                float2 v = make_float2(acc2[ntl][2] + bb0, acc2[ntl][3] + bb1);
                *(float2*)(out + (size_t)gr_hi * D_OUT + col) = v;
            }
        }
    }
}

// ---------------------------------------------------------------------------
// Launch. Inputs: x[f32], edge_index[i32 2xE], W1, b1, W2, b2.
// ---------------------------------------------------------------------------
extern "C" void kernel_launch(void* const* d_in, const int* in_sizes, int n_in,
                              void* d_out, int out_size) {
    const float* x  = (const float*)d_in[0];
    const int*   ei = (const int*)d_in[1];
    const float* W1 = (const float*)d_in[2];
    const float* b1 = (const float*)d_in[3];
    const float* W2 = (const float*)d_in[4];
    const float* b2 = (const float*)d_in[5];
    float* out = (float*)d_out;

    const int N = in_sizes[0] / D_IN;   // 50000
    const int E = in_sizes[1] / 2;      // 800000

    cudaFuncSetAttribute(gin_mlp, cudaFuncAttributeMaxDynamicSharedMemorySize,
                         SMEM_BYTES);

    int n4 = N * (D_IN / 4);
    gin_copy<<<(n4 + 255) / 256, 256>>>(x, n4);
    gin_prep<<<128, 256>>>(W1, W2);

    int work = E * 16;
    gin_scatter<<<(work + 255) / 256, 256>>>(x, ei, E);

    gin_mlp<<<(N + 127) / 128, 512, SMEM_BYTES>>>(b1, b2, out, N);
}